// round 3
// baseline (speedup 1.0000x reference)
#include <cuda_runtime.h>
#include <cuda_bf16.h>
#include <stdint.h>

// Problem constants (fixed by the dataset).
#define N_NODES 65536
#define N_EDGES 1048576
#define D 64

// Scratch: __device__ globals (no allocation allowed in kernel_launch).
// 16B-aligned so float4 LDG/STG.128 on them is always legal.
__device__ __align__(16) float g_h[N_NODES * D];  // h = x @ W (16 MB)
__device__ float g_dinv[N_NODES];                 // deg^{-1/2}
__device__ int   g_deg[N_NODES];                  // degree incl. self-loop

// ---------------------------------------------------------------------------
// Kernel 1: init degrees to 1 (self-loop).
__global__ void k_deg_init() {
    int i = blockIdx.x * blockDim.x + threadIdx.x;
    if (i < N_NODES) g_deg[i] = 1;
}

// Kernel 2: count in-degree at targets. Edge index is INT32, layout [2, E].
__global__ void k_deg_count(const int* __restrict__ ei) {
    int e = blockIdx.x * blockDim.x + threadIdx.x;
    if (e < N_EDGES) {
        int dst = ei[N_EDGES + e];
        atomicAdd(&g_deg[dst], 1);   // RED.ADD (no return)
    }
}

// Kernel 3: dinv = rsqrt(deg). deg >= 1 always (self-loop), no zero case.
__global__ void k_dinv() {
    int i = blockIdx.x * blockDim.x + threadIdx.x;
    if (i < N_NODES) g_dinv[i] = rsqrtf((float)g_deg[i]);
}

// ---------------------------------------------------------------------------
// Kernel 4: h = x @ W, fused epilogue: out[i] = h[i]*dinv[i]^2 + b  (self-loop
// term + bias). Each block computes a 64x64 tile (64 rows of h), 256 threads,
// each thread a 4x4 micro-tile using float4 LDS.
__global__ __launch_bounds__(256) void k_gemm(const float* __restrict__ x,
                                              const float* __restrict__ W,
                                              const float* __restrict__ b,
                                              float* __restrict__ out) {
    __shared__ __align__(16) float xs[64 * 64];  // x tile, TRANSPOSED: xs[k*64 + row]
    __shared__ __align__(16) float ws[64 * 64];  // W, row-major: ws[k*64 + j]

    const int tid = threadIdx.x;
    const int rowBase = blockIdx.x * 64;

    // Load W (4096 floats, 16 per thread).
    for (int i = tid; i < 64 * 64; i += 256) ws[i] = W[i];

    // Load x tile transposed. Each thread: row = tid&63, quarter kq = tid>>6,
    // loads 4 float4 along k and scatters into xs[k][row].
    {
        int row = tid & 63;
        int kq  = tid >> 6;  // 0..3 -> k range [kq*16, kq*16+16)
        const float4* xrow = (const float4*)&x[(size_t)(rowBase + row) * D];
        #pragma unroll
        for (int q = 0; q < 4; q++) {
            int k0 = kq * 16 + q * 4;
            float4 v = xrow[k0 >> 2];
            xs[(k0 + 0) * 64 + row] = v.x;
            xs[(k0 + 1) * 64 + row] = v.y;
            xs[(k0 + 2) * 64 + row] = v.z;
            xs[(k0 + 3) * 64 + row] = v.w;
        }
    }
    __syncthreads();

    const int ty = tid >> 4;   // 0..15 -> rows ty*4 .. ty*4+3
    const int tx = tid & 15;   // 0..15 -> cols tx*4 .. tx*4+3

    float acc[4][4] = {};
    #pragma unroll 16
    for (int k = 0; k < 64; k++) {
        float4 a  = *(const float4*)&xs[k * 64 + ty * 4];
        float4 w4 = *(const float4*)&ws[k * 64 + tx * 4];
        acc[0][0] += a.x * w4.x; acc[0][1] += a.x * w4.y;
        acc[0][2] += a.x * w4.z; acc[0][3] += a.x * w4.w;
        acc[1][0] += a.y * w4.x; acc[1][1] += a.y * w4.y;
        acc[1][2] += a.y * w4.z; acc[1][3] += a.y * w4.w;
        acc[2][0] += a.z * w4.x; acc[2][1] += a.z * w4.y;
        acc[2][2] += a.z * w4.z; acc[2][3] += a.z * w4.w;
        acc[3][0] += a.w * w4.x; acc[3][1] += a.w * w4.y;
        acc[3][2] += a.w * w4.z; acc[3][3] += a.w * w4.w;
    }

    // Epilogue: write h, and out = h*dinv^2 + b.
    float4 bv = *(const float4*)&b[tx * 4];
    #pragma unroll
    for (int i = 0; i < 4; i++) {
        int r = rowBase + ty * 4 + i;
        float di = g_dinv[r];
        float s  = di * di;
        float4 hv = make_float4(acc[i][0], acc[i][1], acc[i][2], acc[i][3]);
        *(float4*)&g_h[(size_t)r * D + tx * 4] = hv;
        float4 ov = make_float4(hv.x * s + bv.x, hv.y * s + bv.y,
                                hv.z * s + bv.z, hv.w * s + bv.w);
        *(float4*)&out[(size_t)r * D + tx * 4] = ov;
    }
}

// ---------------------------------------------------------------------------
// Kernel 5: edge scatter. 16 lanes per edge; each lane moves one float4 of
// message and issues 4 scalar RED.F32 (atomicAdd, result unused):
//   out[dst] += h[src] * dinv[src]*dinv[dst]
__global__ __launch_bounds__(256) void k_scatter(const int* __restrict__ ei,
                                                 float* __restrict__ out) {
    long long t = (long long)blockIdx.x * blockDim.x + threadIdx.x;
    int e  = (int)(t >> 4);
    int j4 = ((int)t & 15) * 4;
    if (e >= N_EDGES) return;

    int src = ei[e];
    int dst = ei[N_EDGES + e];
    float norm = g_dinv[src] * g_dinv[dst];

    float4 hv = *(const float4*)&g_h[(size_t)src * D + j4];

    float* p = &out[(size_t)dst * D + j4];
    atomicAdd(p + 0, hv.x * norm);
    atomicAdd(p + 1, hv.y * norm);
    atomicAdd(p + 2, hv.z * norm);
    atomicAdd(p + 3, hv.w * norm);
}

// ---------------------------------------------------------------------------
extern "C" void kernel_launch(void* const* d_in, const int* in_sizes, int n_in,
                              void* d_out, int out_size) {
    const float* x  = (const float*)d_in[0];
    const int*   ei = (const int*)d_in[1];    // [2, E] int32 (JAX x64 disabled)
    const float* W  = (const float*)d_in[2];
    const float* b  = (const float*)d_in[3];
    float* out = (float*)d_out;

    (void)in_sizes; (void)n_in; (void)out_size;

    k_deg_init<<<(N_NODES + 255) / 256, 256>>>();
    k_deg_count<<<(N_EDGES + 255) / 256, 256>>>(ei);
    k_dinv<<<(N_NODES + 255) / 256, 256>>>();
    k_gemm<<<N_NODES / 64, 256>>>(x, W, b, out);

    long long scatter_threads = (long long)N_EDGES * 16;
    k_scatter<<<(unsigned)((scatter_threads + 255) / 256), 256>>>(ei, out);
}

// round 4
// speedup vs baseline: 1.9296x; 1.9296x over previous
#include <cuda_runtime.h>
#include <cuda_bf16.h>
#include <stdint.h>

// Problem constants (fixed by the dataset).
#define N_NODES 65536
#define N_EDGES 1048576
#define D 64

// Scratch: __device__ globals (no allocation allowed in kernel_launch).
// 16B-aligned so float4 LDG/STG.128 on them is always legal.
__device__ __align__(16) float g_h[N_NODES * D];  // h = x @ W (16 MB)
__device__ float g_dinv[N_NODES];                 // deg^{-1/2}
__device__ int   g_deg[N_NODES];                  // degree incl. self-loop

// ---------------------------------------------------------------------------
// Kernel 1: init degrees to 1 (self-loop).
__global__ void k_deg_init() {
    int i = blockIdx.x * blockDim.x + threadIdx.x;
    if (i < N_NODES) g_deg[i] = 1;
}

// Kernel 2: count in-degree at targets. Edge index is INT32, layout [2, E].
__global__ void k_deg_count(const int* __restrict__ ei) {
    int e = blockIdx.x * blockDim.x + threadIdx.x;
    if (e < N_EDGES) {
        int dst = ei[N_EDGES + e];
        atomicAdd(&g_deg[dst], 1);   // RED.ADD (no return)
    }
}

// Kernel 3: dinv = rsqrt(deg). deg >= 1 always (self-loop), no zero case.
__global__ void k_dinv() {
    int i = blockIdx.x * blockDim.x + threadIdx.x;
    if (i < N_NODES) g_dinv[i] = rsqrtf((float)g_deg[i]);
}

// ---------------------------------------------------------------------------
// Kernel 4: h = x @ W, fused epilogue: out[i] = h[i]*dinv[i]^2 + b  (self-loop
// term + bias). Each block computes a 64x64 tile (64 rows of h), 256 threads,
// each thread a 4x4 micro-tile using float4 LDS.
__global__ __launch_bounds__(256) void k_gemm(const float* __restrict__ x,
                                              const float* __restrict__ W,
                                              const float* __restrict__ b,
                                              float* __restrict__ out) {
    __shared__ __align__(16) float xs[64 * 64];  // x tile, TRANSPOSED: xs[k*64 + row]
    __shared__ __align__(16) float ws[64 * 64];  // W, row-major: ws[k*64 + j]

    const int tid = threadIdx.x;
    const int rowBase = blockIdx.x * 64;

    // Load W (4096 floats, 16 per thread).
    for (int i = tid; i < 64 * 64; i += 256) ws[i] = W[i];

    // Load x tile transposed. Each thread: row = tid&63, quarter kq = tid>>6,
    // loads 4 float4 along k and scatters into xs[k][row].
    {
        int row = tid & 63;
        int kq  = tid >> 6;  // 0..3 -> k range [kq*16, kq*16+16)
        const float4* xrow = (const float4*)&x[(size_t)(rowBase + row) * D];
        #pragma unroll
        for (int q = 0; q < 4; q++) {
            int k0 = kq * 16 + q * 4;
            float4 v = xrow[k0 >> 2];
            xs[(k0 + 0) * 64 + row] = v.x;
            xs[(k0 + 1) * 64 + row] = v.y;
            xs[(k0 + 2) * 64 + row] = v.z;
            xs[(k0 + 3) * 64 + row] = v.w;
        }
    }
    __syncthreads();

    const int ty = tid >> 4;   // 0..15 -> rows ty*4 .. ty*4+3
    const int tx = tid & 15;   // 0..15 -> cols tx*4 .. tx*4+3

    float acc[4][4] = {};
    #pragma unroll 16
    for (int k = 0; k < 64; k++) {
        float4 a  = *(const float4*)&xs[k * 64 + ty * 4];
        float4 w4 = *(const float4*)&ws[k * 64 + tx * 4];
        acc[0][0] += a.x * w4.x; acc[0][1] += a.x * w4.y;
        acc[0][2] += a.x * w4.z; acc[0][3] += a.x * w4.w;
        acc[1][0] += a.y * w4.x; acc[1][1] += a.y * w4.y;
        acc[1][2] += a.y * w4.z; acc[1][3] += a.y * w4.w;
        acc[2][0] += a.z * w4.x; acc[2][1] += a.z * w4.y;
        acc[2][2] += a.z * w4.z; acc[2][3] += a.z * w4.w;
        acc[3][0] += a.w * w4.x; acc[3][1] += a.w * w4.y;
        acc[3][2] += a.w * w4.z; acc[3][3] += a.w * w4.w;
    }

    // Epilogue: write h, and out = h*dinv^2 + b.
    float4 bv = *(const float4*)&b[tx * 4];
    #pragma unroll
    for (int i = 0; i < 4; i++) {
        int r = rowBase + ty * 4 + i;
        float di = g_dinv[r];
        float s  = di * di;
        float4 hv = make_float4(acc[i][0], acc[i][1], acc[i][2], acc[i][3]);
        *(float4*)&g_h[(size_t)r * D + tx * 4] = hv;
        float4 ov = make_float4(hv.x * s + bv.x, hv.y * s + bv.y,
                                hv.z * s + bv.z, hv.w * s + bv.w);
        *(float4*)&out[(size_t)r * D + tx * 4] = ov;
    }
}

// ---------------------------------------------------------------------------
// Kernel 5: edge scatter. 16 lanes per edge; each lane moves one float4 of
// message with ONE 128-bit vectorized reduction (sm_90+):
//   out[dst] += h[src] * dinv[src]*dinv[dst]
// 4x fewer atomic ops than scalar RED.F32; same L2 byte traffic.
__global__ __launch_bounds__(256) void k_scatter(const int* __restrict__ ei,
                                                 float* __restrict__ out) {
    long long t = (long long)blockIdx.x * blockDim.x + threadIdx.x;
    int e  = (int)(t >> 4);
    int j4 = ((int)t & 15) * 4;
    if (e >= N_EDGES) return;

    int src = ei[e];
    int dst = ei[N_EDGES + e];
    float norm = g_dinv[src] * g_dinv[dst];

    float4 hv = *(const float4*)&g_h[(size_t)src * D + j4];
    float4 m = make_float4(hv.x * norm, hv.y * norm, hv.z * norm, hv.w * norm);

    float* p = &out[(size_t)dst * D + j4];
    asm volatile("red.global.add.v4.f32 [%0], {%1, %2, %3, %4};"
                 :: "l"(p), "f"(m.x), "f"(m.y), "f"(m.z), "f"(m.w)
                 : "memory");
}

// ---------------------------------------------------------------------------
extern "C" void kernel_launch(void* const* d_in, const int* in_sizes, int n_in,
                              void* d_out, int out_size) {
    const float* x  = (const float*)d_in[0];
    const int*   ei = (const int*)d_in[1];    // [2, E] int32 (JAX x64 disabled)
    const float* W  = (const float*)d_in[2];
    const float* b  = (const float*)d_in[3];
    float* out = (float*)d_out;

    (void)in_sizes; (void)n_in; (void)out_size;

    k_deg_init<<<(N_NODES + 255) / 256, 256>>>();
    k_deg_count<<<(N_EDGES + 255) / 256, 256>>>(ei);
    k_dinv<<<(N_NODES + 255) / 256, 256>>>();
    k_gemm<<<N_NODES / 64, 256>>>(x, W, b, out);

    long long scatter_threads = (long long)N_EDGES * 16;
    k_scatter<<<(unsigned)((scatter_threads + 255) / 256), 256>>>(ei, out);
}

// round 5
// speedup vs baseline: 1.9840x; 1.0282x over previous
#include <cuda_runtime.h>
#include <cuda_bf16.h>
#include <stdint.h>

// Problem constants (fixed by the dataset).
#define N_NODES 65536
#define N_EDGES 1048576
#define D 64

// Scratch: __device__ globals (no allocation allowed in kernel_launch).
__device__ __align__(16) float g_h[N_NODES * D];  // h = x @ W (16 MB)
__device__ float g_dinv[N_NODES];                 // deg^{-1/2}
__device__ int   g_deg[N_NODES];                  // degree incl. self-loop

// ---------------------------------------------------------------------------
// Kernel 1: init degrees to 1 (self-loop).
__global__ void k_deg_init() {
    int i = blockIdx.x * blockDim.x + threadIdx.x;
    if (i < N_NODES) g_deg[i] = 1;
}

// Kernel 2: count in-degree at targets. 4 edges per thread via int4.
__global__ void k_deg_count(const int* __restrict__ ei) {
    int t = blockIdx.x * blockDim.x + threadIdx.x;
    if (t < N_EDGES / 4) {
        int4 d = ((const int4*)(ei + N_EDGES))[t];
        atomicAdd(&g_deg[d.x], 1);
        atomicAdd(&g_deg[d.y], 1);
        atomicAdd(&g_deg[d.z], 1);
        atomicAdd(&g_deg[d.w], 1);
    }
}

// Kernel 3: dinv = rsqrt(deg). deg >= 1 always (self-loop).
__global__ void k_dinv() {
    int i = blockIdx.x * blockDim.x + threadIdx.x;
    if (i < N_NODES) g_dinv[i] = rsqrtf((float)g_deg[i]);
}

// ---------------------------------------------------------------------------
// Kernel 4: h = x @ W, fused epilogue out[i] = h[i]*dinv[i]^2 + b.
// 128-row tile per block, 256 threads, 8x4 micro-tile per thread.
// 512 blocks x 4 CTA/SM occupancy -> whole GEMM in one wave.
__global__ __launch_bounds__(256) void k_gemm(const float* __restrict__ x,
                                              const float* __restrict__ W,
                                              const float* __restrict__ b,
                                              float* __restrict__ out) {
    __shared__ __align__(16) float xs[64 * 128];  // transposed: xs[k*128 + row] (32KB)
    __shared__ __align__(16) float ws[64 * 64];   // row-major: ws[k*64 + j]   (16KB)

    const int tid = threadIdx.x;
    const int rowBase = blockIdx.x * 128;

    // Load W: 1024 float4, 4 per thread.
    {
        const float4* Wv = (const float4*)W;
        float4* wsv = (float4*)ws;
        #pragma unroll
        for (int q = 0; q < 4; q++) wsv[tid + q * 256] = Wv[tid + q * 256];
    }

    // Load x tile transposed: row = tid&127, k-half kq = tid>>7 (32 k's = 8 float4).
    {
        int row = tid & 127;
        int kq  = tid >> 7;  // 0..1
        const float4* xrow = (const float4*)&x[(size_t)(rowBase + row) * D];
        #pragma unroll
        for (int q = 0; q < 8; q++) {
            int k0 = kq * 32 + q * 4;
            float4 v = xrow[k0 >> 2];
            xs[(k0 + 0) * 128 + row] = v.x;
            xs[(k0 + 1) * 128 + row] = v.y;
            xs[(k0 + 2) * 128 + row] = v.z;
            xs[(k0 + 3) * 128 + row] = v.w;
        }
    }
    __syncthreads();

    const int ty = tid >> 4;   // 0..15 -> rows ty*8 .. ty*8+7
    const int tx = tid & 15;   // 0..15 -> cols tx*4 .. tx*4+3

    float acc[8][4] = {};
    #pragma unroll 8
    for (int k = 0; k < 64; k++) {
        float4 a0 = *(const float4*)&xs[k * 128 + ty * 8];
        float4 a1 = *(const float4*)&xs[k * 128 + ty * 8 + 4];
        float4 w4 = *(const float4*)&ws[k * 64 + tx * 4];
        float av[8] = {a0.x, a0.y, a0.z, a0.w, a1.x, a1.y, a1.z, a1.w};
        #pragma unroll
        for (int i = 0; i < 8; i++) {
            acc[i][0] += av[i] * w4.x;
            acc[i][1] += av[i] * w4.y;
            acc[i][2] += av[i] * w4.z;
            acc[i][3] += av[i] * w4.w;
        }
    }

    // Epilogue: write h, and out = h*dinv^2 + b (self-loop + bias folded in).
    float4 bv = *(const float4*)&b[tx * 4];
    #pragma unroll
    for (int i = 0; i < 8; i++) {
        int r = rowBase + ty * 8 + i;
        float di = g_dinv[r];
        float s  = di * di;
        float4 hv = make_float4(acc[i][0], acc[i][1], acc[i][2], acc[i][3]);
        *(float4*)&g_h[(size_t)r * D + tx * 4] = hv;
        float4 ov = make_float4(hv.x * s + bv.x, hv.y * s + bv.y,
                                hv.z * s + bv.z, hv.w * s + bv.w);
        *(float4*)&out[(size_t)r * D + tx * 4] = ov;
    }
}

// ---------------------------------------------------------------------------
// Kernel 5: edge scatter (UNCHANGED from R4 win — at the LTS byte floor).
// 16 lanes per edge; each lane: one float4 gather + one red.global.add.v4.f32.
__global__ __launch_bounds__(256) void k_scatter(const int* __restrict__ ei,
                                                 float* __restrict__ out) {
    long long t = (long long)blockIdx.x * blockDim.x + threadIdx.x;
    int e  = (int)(t >> 4);
    int j4 = ((int)t & 15) * 4;
    if (e >= N_EDGES) return;

    int src = ei[e];
    int dst = ei[N_EDGES + e];
    float norm = g_dinv[src] * g_dinv[dst];

    float4 hv = *(const float4*)&g_h[(size_t)src * D + j4];
    float4 m = make_float4(hv.x * norm, hv.y * norm, hv.z * norm, hv.w * norm);

    float* p = &out[(size_t)dst * D + j4];
    asm volatile("red.global.add.v4.f32 [%0], {%1, %2, %3, %4};"
                 :: "l"(p), "f"(m.x), "f"(m.y), "f"(m.z), "f"(m.w)
                 : "memory");
}

// ---------------------------------------------------------------------------
extern "C" void kernel_launch(void* const* d_in, const int* in_sizes, int n_in,
                              void* d_out, int out_size) {
    const float* x  = (const float*)d_in[0];
    const int*   ei = (const int*)d_in[1];    // [2, E] int32
    const float* W  = (const float*)d_in[2];
    const float* b  = (const float*)d_in[3];
    float* out = (float*)d_out;

    (void)in_sizes; (void)n_in; (void)out_size;

    k_deg_init<<<(N_NODES + 255) / 256, 256>>>();
    k_deg_count<<<(N_EDGES / 4 + 255) / 256, 256>>>(ei);
    k_dinv<<<(N_NODES + 255) / 256, 256>>>();
    k_gemm<<<N_NODES / 128, 256>>>(x, W, b, out);

    long long scatter_threads = (long long)N_EDGES * 16;
    k_scatter<<<(unsigned)((scatter_threads + 255) / 256), 256>>>(ei, out);
}